// round 2
// baseline (speedup 1.0000x reference)
#include <cuda_runtime.h>
#include <math.h>

// SigmoidGatedCRFLoss on GB300 — pairwise-collapsed formulation.
// loss = [ Σ_{p,q} md(p)·ms(q)·g(Δ)·(0.9·e^{-50|Δrgb|²}+0.1)·(s_p(1-s_q)+s_q(1-s_p)) ] / max(Σ md, 1)

#define RAD   5
#define DIAM  11
#define TW    32
#define TH    8
#define HW_   (TW + 2 * RAD)   // 42
#define HH_   (TH + 2 * RAD)   // 18
#define HSZ   (HW_ * HH_)      // 756

__device__ double g_num_acc;
__device__ double g_den_acc;

__global__ void zero_acc_kernel() {
    g_num_acc = 0.0;
    g_den_acc = 0.0;
}

__global__ __launch_bounds__(TW * TH) void crf_loss_kernel(
    const float* __restrict__ x,      // [N,3,H,W]
    const float* __restrict__ y,      // [N,H,W]
    const float* __restrict__ msrc,   // [N,1,H,W]
    const float* __restrict__ mdst,   // [N,1,H,W]
    int H, int W)
{
    __shared__ float4 sRGBA[HSZ];        // r, g, b, A = ms*s
    __shared__ float  sB[HSZ];           // B = ms*(1-s)
    __shared__ float  sG[DIAM * DIAM];   // spatial gaussian table (center = 0)
    __shared__ float  red[16];           // block reduction scratch

    const int n   = blockIdx.z;
    const int tx0 = blockIdx.x * TW;
    const int ty0 = blockIdx.y * TH;
    const int tid = threadIdx.y * TW + threadIdx.x;
    const int HWp = H * W;

    const float* __restrict__ xr = x + (size_t)n * 3 * HWp;
    const float* __restrict__ xg = xr + HWp;
    const float* __restrict__ xb = xr + 2 * HWp;
    const float* __restrict__ yp = y    + (size_t)n * HWp;
    const float* __restrict__ mp = msrc + (size_t)n * HWp;
    const float* __restrict__ dp = mdst + (size_t)n * HWp;

    // Spatial gaussian table: g = exp(-0.5*(dx^2+dy^2)/36), center zeroed
    // (implements kernels[:,:,center]=0 for BOTH descriptors at once).
    if (tid < DIAM * DIAM) {
        int dy = tid / DIAM - RAD;
        int dx = tid % DIAM - RAD;
        float g = __expf(-0.5f * (float)(dx * dx + dy * dy) * (1.0f / 36.0f));
        if (dx == 0 && dy == 0) g = 0.0f;
        sG[tid] = g;
    }

    // Halo load: 756 entries, 256 threads -> 3 passes. OOB -> A=B=0 which
    // reproduces unfold's zero padding of the binarized mask exactly.
    for (int i = tid; i < HSZ; i += TW * TH) {
        int ly = i / HW_;
        int lx = i - ly * HW_;
        int gy = ty0 + ly - RAD;
        int gx = tx0 + lx - RAD;
        float r = 0.f, g = 0.f, b = 0.f, A = 0.f, B = 0.f;
        if (gx >= 0 && gx < W && gy >= 0 && gy < H) {
            int idx = gy * W + gx;
            float ms = mp[idx];
            if (isnan(ms) || ms < 1.0f) ms = 0.0f;   // binarize (keeps value if >=1)
            float yv = yp[idx];
            float s  = 1.0f / (1.0f + __expf(-yv));
            r = xr[idx]; g = xg[idx]; b = xb[idx];
            A = ms * s;
            B = ms * (1.0f - s);
        }
        sRGBA[i] = make_float4(r, g, b, A);
        sB[i]    = B;
    }
    __syncthreads();

    const int px = tx0 + threadIdx.x;
    const int py = ty0 + threadIdx.y;

    float num = 0.0f;   // this pixel's numerator contribution
    float mdv = 0.0f;   // this pixel's binarized mask_dst (denominator term)

    if (px < W && py < H) {
        int idx = py * W + px;
        float md = dp[idx];
        if (isnan(md) || md < 1.0f) md = 0.0f;
        mdv = md;

        int ci = (threadIdx.y + RAD) * HW_ + (threadIdx.x + RAD);
        float4 c = sRGBA[ci];
        float yv = yp[idx];
        float sp = 1.0f / (1.0f + __expf(-yv));

        float SA = 0.0f, SB = 0.0f;
        for (int dy = 0; dy < DIAM; dy++) {       // outer rolled: keeps I$ small
            int rowbase = (threadIdx.y + dy) * HW_ + threadIdx.x;
            #pragma unroll
            for (int dx = 0; dx < DIAM; dx++) {   // inner fully unrolled
                float4 q  = sRGBA[rowbase + dx];
                float  Bq = sB[rowbase + dx];
                float dr = q.x - c.x;
                float dg = q.y - c.y;
                float db = q.z - c.z;
                float d2 = fmaf(dr, dr, fmaf(dg, dg, db * db));
                float e  = __expf(-50.0f * d2);
                float w  = sG[dy * DIAM + dx] * fmaf(0.9f, e, 0.1f);
                SA = fmaf(w, q.w, SA);
                SB = fmaf(w, Bq, SB);
            }
        }
        num = mdv * fmaf(sp, SB, (1.0f - sp) * SA);
    }

    // Block reduction: warp shuffle, then warp leaders -> smem -> thread 0.
    #pragma unroll
    for (int off = 16; off > 0; off >>= 1) {
        num += __shfl_down_sync(0xffffffffu, num, off);
        mdv += __shfl_down_sync(0xffffffffu, mdv, off);
    }
    int wid = tid >> 5, lid = tid & 31;
    if (lid == 0) { red[wid] = num; red[8 + wid] = mdv; }
    __syncthreads();
    if (tid == 0) {
        float ns = 0.f, ds = 0.f;
        #pragma unroll
        for (int i = 0; i < 8; i++) { ns += red[i]; ds += red[8 + i]; }
        atomicAdd(&g_num_acc, (double)ns);
        atomicAdd(&g_den_acc, (double)ds);
    }
}

__global__ void finalize_kernel(float* __restrict__ out) {
    double d = g_den_acc;
    if (d < 1.0) d = 1.0;
    out[0] = (float)(g_num_acc / d);
}

extern "C" void kernel_launch(void* const* d_in, const int* in_sizes, int n_in,
                              void* d_out, int out_size) {
    const float* x    = (const float*)d_in[0];
    const float* y    = (const float*)d_in[1];
    const float* msrc = (const float*)d_in[2];
    const float* mdst = (const float*)d_in[3];
    float* out = (float*)d_out;

    const int H = 256, W = 256;
    const int N = in_sizes[1] / (H * W);

    zero_acc_kernel<<<1, 1>>>();
    dim3 block(TW, TH, 1);
    dim3 grid((W + TW - 1) / TW, (H + TH - 1) / TH, N);
    crf_loss_kernel<<<grid, block>>>(x, y, msrc, mdst, H, W);
    finalize_kernel<<<1, 1>>>(out);
}

// round 3
// speedup vs baseline: 1.2162x; 1.2162x over previous
#include <cuda_runtime.h>
#include <math.h>

// SigmoidGatedCRFLoss, pairwise-collapsed, single fused kernel.
// loss = [ Σ_{p,q} md(p)·ms(q)·g(Δ)·(0.9·e^{-50|Δrgb|²}+0.1)·(s_p(1-s_q)+s_q(1-s_p)) ] / max(Σ md, 1)
//
// Per pixel p:  contrib = md_p · ( s_p·SB + (1-s_p)·SA ),
//   SA = Σ_q w(p,q)·A_q,  SB = Σ_q w(p,q)·B_q,  A=ms·s, B=ms·(1-s)
//   w = G9(Δxy)·(e_rgb + 1/9),  G9 = 0.9·exp(-(dx²+dy²)/72) (0 at center)
//   e_rgb = 2^(-(Σ diff²)) with rgb pre-scaled by sqrt(50·log2 e)  == exp(-50|Δrgb|²)

#define RAD   5
#define DIAM  11
#define BX    16            // threads in x
#define BY    8             // threads in y
#define TW    (BX * 2)      // 32-pixel-wide tile (2 px per thread)
#define TH    BY            // 8
#define HW_   (TW + 2*RAD)  // 42
#define HH_   (TH + 2*RAD)  // 18
#define HSZ   (HW_ * HH_)   // 756
#define HALFW ((HW_ + 1)/2) // 21
#define NT    (BX * BY)     // 128 threads

#define RGB_SCALE 8.493218f     // sqrt(50 * log2(e))

__device__ double   g_num;
__device__ double   g_den;
__device__ unsigned g_ticket;

__device__ __forceinline__ float fast_ex2(float x) {
    float r;
    asm("ex2.approx.f32 %0, %1;" : "=f"(r) : "f"(x));
    return r;
}

__global__ __launch_bounds__(NT, 4) void crf_loss_kernel(
    const float* __restrict__ x,      // [N,3,H,W]
    const float* __restrict__ y,      // [N,H,W]
    const float* __restrict__ msrc,   // [N,1,H,W]
    const float* __restrict__ mdst,   // [N,1,H,W]
    float* __restrict__ out,
    int H, int W, unsigned nblocks)
{
    // even/odd column split -> unit-stride lane addressing (no bank conflicts)
    __shared__ float4 sEv[HH_][HALFW];   // r,g,b (scaled), A = ms*s   (even cols)
    __shared__ float4 sOd[HH_][HALFW];   // (odd cols)
    __shared__ float  sBEv[HH_][HALFW];  // B = ms*(1-s)
    __shared__ float  sBOd[HH_][HALFW];
    __shared__ __align__(16) float sG[DIAM * 12];  // 0.9*gauss, rows padded to 12
    __shared__ float  red[8];

    const int n   = blockIdx.z;
    const int tx0 = blockIdx.x * TW;
    const int ty0 = blockIdx.y * TH;
    const int tid = threadIdx.y * BX + threadIdx.x;
    const int HWp = H * W;

    const float* __restrict__ xr = x + (size_t)n * 3 * HWp;
    const float* __restrict__ xg = xr + HWp;
    const float* __restrict__ xb = xr + 2 * HWp;
    const float* __restrict__ yp = y    + (size_t)n * HWp;
    const float* __restrict__ mp = msrc + (size_t)n * HWp;
    const float* __restrict__ dp = mdst + (size_t)n * HWp;

    // Spatial gaussian table (row-padded to 12): G9 = 0.9*exp(-(dx^2+dy^2)/72),
    // center forced to 0 (implements kernels[:,:,center]=0 for both descriptors).
    for (int i = tid; i < DIAM * 12; i += NT) {
        int dy = i / 12, dx = i % 12;
        float g = 0.0f;
        if (dx < DIAM) {
            int ddx = dx - RAD, ddy = dy - RAD;
            g = 0.9f * __expf(-(float)(ddx*ddx + ddy*ddy) * (1.0f / 72.0f));
            if (ddx == 0 && ddy == 0) g = 0.0f;
        }
        sG[i] = g;
    }

    // Halo fill. OOB -> all zeros == unfold's zero padding of binarized mask.
    for (int i = tid; i < HSZ; i += NT) {
        int ly = i / HW_;
        int lx = i - ly * HW_;
        int gy = ty0 + ly - RAD;
        int gx = tx0 + lx - RAD;
        float r = 0.f, g = 0.f, b = 0.f, A = 0.f, B = 0.f;
        if (gx >= 0 && gx < W && gy >= 0 && gy < H) {
            int idx = gy * W + gx;
            float ms = mp[idx];
            if (isnan(ms) || ms < 1.0f) ms = 0.0f;    // binarize, keep value if >=1
            float s = 1.0f / (1.0f + __expf(-yp[idx]));
            r = xr[idx] * RGB_SCALE;
            g = xg[idx] * RGB_SCALE;
            b = xb[idx] * RGB_SCALE;
            A = ms * s;
            B = ms - A;                               // ms*(1-s)
        }
        float4 v = make_float4(r, g, b, A);
        int h = lx >> 1;
        if (lx & 1) { sOd[ly][h] = v; sBOd[ly][h] = B; }
        else        { sEv[ly][h] = v; sBEv[ly][h] = B; }
    }
    __syncthreads();

    const int cx = threadIdx.x;           // 0..15
    const int cy = threadIdx.y;           // 0..7
    // center halo-local cols: p0 = 2cx+5 (odd), p1 = 2cx+6 (even)
    const float4 c0 = sOd[cy + RAD][cx + 2];
    const float4 c1 = sEv[cy + RAD][cx + 3];

    float SA0 = 0.f, SB0 = 0.f, SA1 = 0.f, SB1 = 0.f;

    #define TAP(q, Bq, Gv, c, SA, SB) do {                                   \
        float dr_ = (q).x - (c).x;                                           \
        float dg_ = (q).y - (c).y;                                           \
        float db_ = (q).z - (c).z;                                           \
        float d2n_ = fmaf(dr_, -dr_, fmaf(dg_, -dg_, db_ * (-db_)));         \
        float e_  = fast_ex2(d2n_);                                          \
        float w_  = (e_ + 0.11111111f) * (Gv);                               \
        SA = fmaf(w_, (q).w, SA);                                            \
        SB = fmaf(w_, (Bq), SB);                                             \
    } while (0)

    for (int dy = 0; dy < DIAM; dy++) {
        const int row = cy + dy;
        const float4* __restrict__ ev  = &sEv[row][cx];
        const float4* __restrict__ od  = &sOd[row][cx];
        const float*  __restrict__ bev = &sBEv[row][cx];
        const float*  __restrict__ bod = &sBOd[row][cx];

        float gr[12];
        ((float4*)gr)[0] = *(const float4*)&sG[dy * 12 + 0];
        ((float4*)gr)[1] = *(const float4*)&sG[dy * 12 + 4];
        ((float4*)gr)[2] = *(const float4*)&sG[dy * 12 + 8];

        #pragma unroll
        for (int j = 0; j < 12; j++) {
            // window col (local) = 2cx + j; even j -> Ev[cx + j/2], odd -> Od[cx + (j-1)/2]
            float4 q;
            float  Bq;
            if (j & 1) { q = od[(j - 1) >> 1]; Bq = bod[(j - 1) >> 1]; }
            else       { q = ev[j >> 1];       Bq = bev[j >> 1];       }
            if (j < 11) TAP(q, Bq, gr[j],     c0, SA0, SB0);  // pixel0 dx index = j
            if (j > 0)  TAP(q, Bq, gr[j - 1], c1, SA1, SB1);  // pixel1 dx index = j-1
        }
    }

    // Center-pixel combine
    const int px0 = tx0 + 2 * cx;
    const int py  = ty0 + cy;
    float num = 0.f, den = 0.f;
    if (py < H) {
        if (px0 < W) {
            int idx = py * W + px0;
            float md = dp[idx];
            if (isnan(md) || md < 1.0f) md = 0.0f;
            float sp = 1.0f / (1.0f + __expf(-yp[idx]));
            num += md * fmaf(sp, SB0, (1.0f - sp) * SA0);
            den += md;
        }
        if (px0 + 1 < W) {
            int idx = py * W + px0 + 1;
            float md = dp[idx];
            if (isnan(md) || md < 1.0f) md = 0.0f;
            float sp = 1.0f / (1.0f + __expf(-yp[idx]));
            num += md * fmaf(sp, SB1, (1.0f - sp) * SA1);
            den += md;
        }
    }

    // Block reduction
    #pragma unroll
    for (int off = 16; off > 0; off >>= 1) {
        num += __shfl_down_sync(0xffffffffu, num, off);
        den += __shfl_down_sync(0xffffffffu, den, off);
    }
    int wid = tid >> 5, lid = tid & 31;
    if (lid == 0) { red[wid] = num; red[4 + wid] = den; }
    __syncthreads();

    if (tid == 0) {
        float ns = red[0] + red[1] + red[2] + red[3];
        float ds = red[4] + red[5] + red[6] + red[7];
        atomicAdd(&g_num, (double)ns);
        atomicAdd(&g_den, (double)ds);
        __threadfence();
        unsigned old = atomicAdd(&g_ticket, 1u);
        if (old == nblocks - 1u) {          // last block finalizes + resets
            double nn = g_num;
            double dd = g_den;
            if (dd < 1.0) dd = 1.0;
            out[0] = (float)(nn / dd);
            g_num = 0.0;
            g_den = 0.0;
            g_ticket = 0u;
        }
    }
}

extern "C" void kernel_launch(void* const* d_in, const int* in_sizes, int n_in,
                              void* d_out, int out_size) {
    const float* x    = (const float*)d_in[0];
    const float* y    = (const float*)d_in[1];
    const float* msrc = (const float*)d_in[2];
    const float* mdst = (const float*)d_in[3];
    float* out = (float*)d_out;

    const int H = 256, W = 256;
    const int N = in_sizes[1] / (H * W);

    dim3 block(BX, BY, 1);
    dim3 grid((W + TW - 1) / TW, (H + TH - 1) / TH, N);
    unsigned nblocks = grid.x * grid.y * grid.z;
    crf_loss_kernel<<<grid, block>>>(x, y, msrc, mdst, out, H, W, nblocks);
}